// round 1
// baseline (speedup 1.0000x reference)
#include <cuda_runtime.h>

#define N_   4
#define C_   128
#define D_   16
#define H_   64
#define W_   64
#define L_   512
#define TAPS 27

// Scratch (allocation-free rule: __device__ globals)
__device__ float g_style[N_ * C_];                    // [n][i]
__device__ float g_wmod[N_ * C_ * TAPS * C_];         // [n][i][tap][o]  (transposed for conv smem loads)

// ---------------------------------------------------------------------------
// Kernel 1: style[n][i] = latent[n] . fc_w[i] + fc_b[i]
// ---------------------------------------------------------------------------
__global__ void style_kernel(const float* __restrict__ latent,
                             const float* __restrict__ fc_w,
                             const float* __restrict__ fc_b) {
    int n = blockIdx.x;
    int i = threadIdx.x;
    const float* lat  = latent + n * L_;
    const float* wrow = fc_w + i * L_;
    float acc = 0.f;
#pragma unroll 8
    for (int l = 0; l < L_; ++l) acc = fmaf(lat[l], wrow[l], acc);
    g_style[n * C_ + i] = acc + fc_b[i];
}

// ---------------------------------------------------------------------------
// Kernel 2: modulate + demodulate, store transposed as [n][i][tap][o]
// block = (o, n), 128 threads over i
// ---------------------------------------------------------------------------
__global__ void modw_kernel(const float* __restrict__ weight) {
    int o = blockIdx.x;
    int n = blockIdx.y;
    int i = threadIdx.x;

    float s = g_style[n * C_ + i];
    const float* wp = weight + (o * C_ + i) * TAPS;   // weight[o][i][tap]

    float v[TAPS];
    float ss = 0.f;
#pragma unroll
    for (int t = 0; t < TAPS; ++t) {
        v[t] = wp[t] * s;
        ss = fmaf(v[t], v[t], ss);
    }

    __shared__ float red[C_];
    red[i] = ss;
    __syncthreads();
#pragma unroll
    for (int st = 64; st > 0; st >>= 1) {
        if (i < st) red[i] += red[i + st];
        __syncthreads();
    }
    float r = rsqrtf(red[0] + 1e-8f);

    float* outp = g_wmod + ((size_t)(n * C_ + i) * TAPS) * C_ + o;
#pragma unroll
    for (int t = 0; t < TAPS; ++t) outp[t * C_] = v[t] * r;
}

// ---------------------------------------------------------------------------
// Kernel 3: the conv. One CTA per (n, d, h): 128 outC x 64 w outputs.
// 128 threads, each computes an 8(o) x 8(w) register tile.
// K-loop over inC: stage 9 padded x-rows (66 wide) + 27x128 weights in smem.
// ---------------------------------------------------------------------------
__global__ __launch_bounds__(128)
void conv_kernel(const float* __restrict__ x, float* __restrict__ out) {
    const int h = blockIdx.x;
    const int d = blockIdx.y;
    const int n = blockIdx.z;
    const int tid = threadIdx.x;
    const int o0 = (tid >> 3) * 8;   // 16 o-groups of 8
    const int w0 = (tid & 7) * 8;    // 8  w-groups of 8

    __shared__ __align__(16) float xs[9][66];
    __shared__ __align__(16) float ws[TAPS][C_];

    float acc[8][8];
#pragma unroll
    for (int a = 0; a < 8; ++a)
#pragma unroll
        for (int b = 0; b < 8; ++b) acc[a][b] = 0.f;

    const float* xn  = x + (size_t)n * C_ * D_ * H_ * W_;
    const float* wmn = g_wmod + (size_t)n * C_ * TAPS * C_;

    for (int i = 0; i < C_; ++i) {
        // Stage the 9 (kd,kh) input rows, width 66 = W+2, with zero padding.
        for (int idx = tid; idx < 9 * 66; idx += 128) {
            int row = idx / 66;
            int j   = idx - row * 66;
            int kd  = row / 3;
            int kh  = row - kd * 3;
            int dd  = d + kd - 1;
            int hh  = h + kh - 1;
            int wi  = j - 1;
            float v = 0.f;
            if ((unsigned)dd < D_ && (unsigned)hh < H_ && (unsigned)wi < W_)
                v = xn[(((size_t)i * D_ + dd) * H_ + hh) * W_ + wi];
            xs[row][j] = v;
        }
        // Stage this channel's 27x128 modulated weights (contiguous, float4).
        {
            const float4* wsrc = (const float4*)(wmn + (size_t)i * TAPS * C_);
            float4* wdst = (float4*)&ws[0][0];
            for (int idx = tid; idx < TAPS * C_ / 4; idx += 128)
                wdst[idx] = wsrc[idx];
        }
        __syncthreads();

        // Rolled over rows (keeps hot body in L0 I$), unrolled inner tiles.
        for (int row = 0; row < 9; ++row) {
            float xv[10];
#pragma unroll
            for (int j = 0; j < 10; ++j) xv[j] = xs[row][w0 + j];
#pragma unroll
            for (int kw = 0; kw < 3; ++kw) {
                float wv[8];
#pragma unroll
                for (int oo = 0; oo < 8; ++oo) wv[oo] = ws[row * 3 + kw][o0 + oo];
#pragma unroll
                for (int oo = 0; oo < 8; ++oo)
#pragma unroll
                    for (int ww = 0; ww < 8; ++ww)
                        acc[oo][ww] = fmaf(wv[oo], xv[kw + ww], acc[oo][ww]);
            }
        }
        __syncthreads();
    }

    // Write 8x8 tile: two float4 stores per o-row, fully coalesced per o.
#pragma unroll
    for (int oo = 0; oo < 8; ++oo) {
        float* dst = out + ((((size_t)n * C_ + o0 + oo) * D_ + d) * H_ + h) * W_ + w0;
        ((float4*)dst)[0] = make_float4(acc[oo][0], acc[oo][1], acc[oo][2], acc[oo][3]);
        ((float4*)dst)[1] = make_float4(acc[oo][4], acc[oo][5], acc[oo][6], acc[oo][7]);
    }
}

// ---------------------------------------------------------------------------
extern "C" void kernel_launch(void* const* d_in, const int* in_sizes, int n_in,
                              void* d_out, int out_size) {
    const float* x      = (const float*)d_in[0];
    const float* latent = (const float*)d_in[1];
    const float* weight = (const float*)d_in[2];
    const float* fc_w   = (const float*)d_in[3];
    const float* fc_b   = (const float*)d_in[4];
    float* out = (float*)d_out;

    style_kernel<<<N_, C_>>>(latent, fc_w, fc_b);
    modw_kernel<<<dim3(C_, N_), C_>>>(weight);
    conv_kernel<<<dim3(H_, D_, N_), 128>>>(x, out);
}

// round 3
// speedup vs baseline: 5.0461x; 5.0461x over previous
#include <cuda_runtime.h>
#include <cuda_fp16.h>
#include <mma.h>
#include <cstdint>

using namespace nvcuda;

#define N_   4
#define C_   128
#define D_   16
#define H_   64
#define W_   64
#define L_   512
#define TAPS 27
#define PD   18
#define PH   66
#define PW   66
#define LDT  72          // smem tile leading dim (halfs): 144B rows, conflict-free

// ---------------------------------------------------------------------------
// Device-global scratch (allocation-free rule). .bss => zero-initialized, and
// we never write the pad borders of g_xT, so they stay zero across replays.
// ---------------------------------------------------------------------------
__device__ float  g_style[N_ * C_];                                    // [n][i]
__device__ __align__(16) __half g_wmod[(size_t)N_ * TAPS * C_ * C_];   // [n][t][o][i]
__device__ __align__(16) __half g_xT[(size_t)N_ * PD * PH * PW * C_];  // padded ch-last

// ---------------------------------------------------------------------------
// cp.async helpers (baseline sm_8x+ PTX; no arch-specific gating)
// ---------------------------------------------------------------------------
__device__ __forceinline__ uint32_t smem_u32(const void* p) {
    uint32_t a;
    asm("{ .reg .u64 t; cvta.to.shared.u64 t, %1; cvt.u32.u64 %0, t; }" : "=r"(a) : "l"(p));
    return a;
}
__device__ __forceinline__ void cp_async16(uint32_t dst, const void* src) {
    asm volatile("cp.async.cg.shared.global [%0], [%1], 16;" :: "r"(dst), "l"(src));
}
#define CP_COMMIT()  asm volatile("cp.async.commit_group;" ::: "memory")
#define CP_WAIT(n)   asm volatile("cp.async.wait_group %0;" :: "n"(n) : "memory")

// ---------------------------------------------------------------------------
// Kernel 1: style[n][i] = latent[n] . fc_w[i] + fc_b[i]   (warp per i)
// grid (C_/4, N_), block 128
// ---------------------------------------------------------------------------
__global__ void style_kernel(const float* __restrict__ latent,
                             const float* __restrict__ fc_w,
                             const float* __restrict__ fc_b) {
    const int n = blockIdx.y;
    const int wid = threadIdx.x >> 5, lid = threadIdx.x & 31;
    const int i = blockIdx.x * 4 + wid;
    const float* lat  = latent + n * L_;
    const float* wrow = fc_w + (size_t)i * L_;
    float acc = 0.f;
#pragma unroll 4
    for (int l = lid; l < L_; l += 32) acc = fmaf(lat[l], wrow[l], acc);
#pragma unroll
    for (int o = 16; o > 0; o >>= 1) acc += __shfl_xor_sync(0xFFFFFFFFu, acc, o);
    if (lid == 0) g_style[n * C_ + i] = acc + fc_b[i];
}

// ---------------------------------------------------------------------------
// Kernel 2: modulate + demodulate -> fp16, layout [n][t][o][i]
// ---------------------------------------------------------------------------
__global__ void modw_kernel(const float* __restrict__ weight) {
    int o = blockIdx.x, n = blockIdx.y, i = threadIdx.x;
    float s = g_style[n * C_ + i];
    const float* wp = weight + (o * C_ + i) * TAPS;
    float v[TAPS];
    float ss = 0.f;
#pragma unroll
    for (int t = 0; t < TAPS; ++t) { v[t] = wp[t] * s; ss = fmaf(v[t], v[t], ss); }
    __shared__ float red[C_];
    red[i] = ss;
    __syncthreads();
#pragma unroll
    for (int st = 64; st > 0; st >>= 1) {
        if (i < st) red[i] += red[i + st];
        __syncthreads();
    }
    float r = rsqrtf(red[0] + 1e-8f);
#pragma unroll
    for (int t = 0; t < TAPS; ++t)
        g_wmod[(((size_t)(n * TAPS + t) * C_) + o) * C_ + i] = __float2half_rn(v[t] * r);
}

// ---------------------------------------------------------------------------
// Kernel 3: transpose x -> padded channels-last fp16 xT[n][d+1][h+1][w+1][i]
// ---------------------------------------------------------------------------
__global__ __launch_bounds__(256)
void transpose_kernel(const float* __restrict__ x) {
    const int h = blockIdx.x, d = blockIdx.y, n = blockIdx.z;
    const int tid = threadIdx.x;
    __shared__ float ts[32][65];
    for (int ic = 0; ic < 4; ++ic) {
        const int i0 = ic * 32;
#pragma unroll
        for (int r = 0; r < 8; ++r) {
            int e = tid + r * 256;
            int ii = e >> 6, w = e & 63;
            ts[ii][w] = x[((((size_t)n * C_ + i0 + ii) * D_ + d) * H_ + h) * W_ + w];
        }
        __syncthreads();
        int w = tid >> 2, g = tid & 3;
        __half hb[8];
#pragma unroll
        for (int j = 0; j < 8; ++j) hb[j] = __float2half_rn(ts[g * 8 + j][w]);
        __half* dst = g_xT + ((((size_t)n * PD + d + 1) * PH + h + 1) * PW + (w + 1)) * C_ + i0 + g * 8;
        *(uint4*)dst = *(const uint4*)hb;
        __syncthreads();
    }
}

// ---------------------------------------------------------------------------
// Kernel 4: conv as 54 accumulated 128x128x64 fp16 GEMMs on HMMA (wmma).
// CTA = (n, d, h-pair). 8 warps, each 64(o) x 32(z), frags persist all stages.
// cp.async double-buffered staging.
// ---------------------------------------------------------------------------
__global__ __launch_bounds__(256)
void conv_kernel(float* __restrict__ out) {
    const int hb = blockIdx.x, d = blockIdx.y, n = blockIdx.z;
    const int h0 = hb * 2;
    const int tid = threadIdx.x, wid = tid >> 5;

    __shared__ __align__(16) __half XS[2][128 * LDT];   // B: z-rows x i (K-major)
    __shared__ __align__(16) __half WS[2][128 * LDT];   // A: o-rows x i (K-major)

    const int wo = wid >> 2;        // 0..1 -> o block of 64
    const int wz = wid & 3;         // 0..3 -> z block of 32

    wmma::fragment<wmma::accumulator, 16, 16, 16, float> c[4][2];
#pragma unroll
    for (int m = 0; m < 4; ++m)
#pragma unroll
        for (int nn = 0; nn < 2; ++nn) wmma::fill_fragment(c[m][nn], 0.f);

    // Per-thread staging coords: 8 chunks of 16B per stage per tile pair.
    // chunk id c in [0,1024): row = c>>3 (0..127), q = c&7 (16B within 64-ch row)
    const __half* xT_n = g_xT + (size_t)n * PD * PH * PW * C_;
    const __half* wm_n = g_wmod + (size_t)n * TAPS * C_ * C_;

    auto prefetch = [&](int s, int buf) {
        const int ic = s >= TAPS;           // 0 or 1
        const int t  = s - ic * TAPS;
        const int kd = t / 9, rr = t - kd * 9;
        const int kh = rr / 3, kw = rr - kh * 3;
        const int i0 = ic * 64;
        const __half* xb = xT_n + (((size_t)(d + kd) * PH + (h0 + kh)) * PW + kw) * C_ + i0;
        const __half* wb = wm_n + (size_t)t * C_ * C_ + i0;
#pragma unroll
        for (int it = 0; it < 4; ++it) {
            int cch = tid + it * 256;
            int row = cch >> 3, q = cch & 7;
            int hh = row >> 6, w = row & 63;
            cp_async16(smem_u32(&XS[buf][row * LDT + q * 8]),
                       xb + ((size_t)(hh * PW + w)) * C_ + q * 8);
            cp_async16(smem_u32(&WS[buf][row * LDT + q * 8]),
                       wb + (size_t)row * C_ + q * 8);
        }
    };

    auto compute = [&](int buf) {
#pragma unroll
        for (int k = 0; k < 4; ++k) {
            wmma::fragment<wmma::matrix_a, 16, 16, 16, __half, wmma::row_major> a[4];
            wmma::fragment<wmma::matrix_b, 16, 16, 16, __half, wmma::col_major> b[2];
#pragma unroll
            for (int m = 0; m < 4; ++m)
                wmma::load_matrix_sync(a[m], &WS[buf][(wo * 64 + m * 16) * LDT + k * 16], LDT);
#pragma unroll
            for (int nn = 0; nn < 2; ++nn)
                wmma::load_matrix_sync(b[nn], &XS[buf][(wz * 32 + nn * 16) * LDT + k * 16], LDT);
#pragma unroll
            for (int m = 0; m < 4; ++m)
#pragma unroll
                for (int nn = 0; nn < 2; ++nn)
                    wmma::mma_sync(c[m][nn], a[m], b[nn], c[m][nn]);
        }
    };

    prefetch(0, 0);
    CP_COMMIT();
    for (int s = 0; s < 2 * TAPS; ++s) {
        if (s < 2 * TAPS - 1) {
            prefetch(s + 1, (s + 1) & 1);
            CP_COMMIT();
            CP_WAIT(1);
        } else {
            CP_WAIT(0);
        }
        __syncthreads();
        compute(s & 1);
        __syncthreads();    // protect buffer before next-next prefetch overwrites
    }

    // Epilogue: store 16x16 fragments straight to gmem (z tiles never straddle hh).
#pragma unroll
    for (int m = 0; m < 4; ++m) {
        const int o = wo * 64 + m * 16;
#pragma unroll
        for (int nn = 0; nn < 2; ++nn) {
            const int z = wz * 32 + nn * 16;
            const int hh = z >> 6, w0 = z & 63;
            float* dst = out + (((size_t)n * C_ + o) * D_ + d) * (H_ * W_) + (h0 + hh) * W_ + w0;
            wmma::store_matrix_sync(dst, c[m][nn], D_ * H_ * W_, wmma::mem_row_major);
        }
    }
}

// ---------------------------------------------------------------------------
extern "C" void kernel_launch(void* const* d_in, const int* in_sizes, int n_in,
                              void* d_out, int out_size) {
    const float* x      = (const float*)d_in[0];
    const float* latent = (const float*)d_in[1];
    const float* weight = (const float*)d_in[2];
    const float* fc_w   = (const float*)d_in[3];
    const float* fc_b   = (const float*)d_in[4];
    float* out = (float*)d_out;

    style_kernel<<<dim3(C_ / 4, N_), 128>>>(latent, fc_w, fc_b);
    modw_kernel<<<dim3(C_, N_), C_>>>(weight);
    transpose_kernel<<<dim3(H_, D_, N_), 256>>>(x);
    conv_kernel<<<dim3(H_ / 2, D_, N_), 256>>>(out);
}

// round 6
// speedup vs baseline: 7.8131x; 1.5483x over previous
#include <cuda_runtime.h>
#include <cuda_fp16.h>
#include <mma.h>
#include <cstdint>

using namespace nvcuda;

#define N_   4
#define C_   128
#define D_   16
#define H_   64
#define W_   64
#define L_   512
#define TAPS 27
#define PD   18
#define PH   66
#define PW   66
#define LDT  72          // smem tile leading dim (halfs): 144B rows, conflict-free
#define NSTAGE 54        // 2 i-chunks x 27 taps

// ---------------------------------------------------------------------------
// Device-global scratch (allocation-free rule). .bss => zero-initialized, and
// we never write the pad borders of g_xT, so they stay zero across replays.
// ---------------------------------------------------------------------------
__device__ float  g_style[N_ * C_];                                    // [n][i]
__device__ __align__(16) __half g_wmod[(size_t)N_ * TAPS * C_ * C_];   // [n][t][o][i]
__device__ __align__(16) __half g_xT[(size_t)N_ * PD * PH * PW * C_];  // padded ch-last

// ---------------------------------------------------------------------------
// cp.async helpers (baseline PTX, no sm_103a-gated features)
// ---------------------------------------------------------------------------
__device__ __forceinline__ uint32_t smem_u32(const void* p) {
    uint32_t a;
    asm("{ .reg .u64 t; cvta.to.shared.u64 t, %1; cvt.u32.u64 %0, t; }" : "=r"(a) : "l"(p));
    return a;
}
__device__ __forceinline__ void cp_async16(uint32_t dst, const void* src) {
    asm volatile("cp.async.cg.shared.global [%0], [%1], 16;" :: "r"(dst), "l"(src));
}
#define CP_COMMIT()  asm volatile("cp.async.commit_group;" ::: "memory")
#define CP_WAIT(n)   asm volatile("cp.async.wait_group %0;" :: "n"(n) : "memory")

// ---------------------------------------------------------------------------
// Kernel 1: style[n][i] = latent[n] . fc_w[i] + fc_b[i]   (warp per i)
// ---------------------------------------------------------------------------
__global__ void style_kernel(const float* __restrict__ latent,
                             const float* __restrict__ fc_w,
                             const float* __restrict__ fc_b) {
    const int n = blockIdx.y;
    const int wid = threadIdx.x >> 5, lid = threadIdx.x & 31;
    const int i = blockIdx.x * 4 + wid;
    const float* lat  = latent + n * L_;
    const float* wrow = fc_w + (size_t)i * L_;
    float acc = 0.f;
#pragma unroll 4
    for (int l = lid; l < L_; l += 32) acc = fmaf(lat[l], wrow[l], acc);
#pragma unroll
    for (int o = 16; o > 0; o >>= 1) acc += __shfl_xor_sync(0xFFFFFFFFu, acc, o);
    if (lid == 0) g_style[n * C_ + i] = acc + fc_b[i];
}

// ---------------------------------------------------------------------------
// Kernel 2: modulate + demodulate -> fp16, layout [n][t][o][i]
// ---------------------------------------------------------------------------
__global__ void modw_kernel(const float* __restrict__ weight) {
    int o = blockIdx.x, n = blockIdx.y, i = threadIdx.x;
    float s = g_style[n * C_ + i];
    const float* wp = weight + (o * C_ + i) * TAPS;
    float v[TAPS];
    float ss = 0.f;
#pragma unroll
    for (int t = 0; t < TAPS; ++t) { v[t] = wp[t] * s; ss = fmaf(v[t], v[t], ss); }
    __shared__ float red[C_];
    red[i] = ss;
    __syncthreads();
#pragma unroll
    for (int st = 64; st > 0; st >>= 1) {
        if (i < st) red[i] += red[i + st];
        __syncthreads();
    }
    float r = rsqrtf(red[0] + 1e-8f);
#pragma unroll
    for (int t = 0; t < TAPS; ++t)
        g_wmod[(((size_t)(n * TAPS + t) * C_) + o) * C_ + i] = __float2half_rn(v[t] * r);
}

// ---------------------------------------------------------------------------
// Kernel 3: transpose x -> padded channels-last fp16 xT[n][d+1][h+1][w+1][i]
// ---------------------------------------------------------------------------
__global__ __launch_bounds__(256)
void transpose_kernel(const float* __restrict__ x) {
    const int h = blockIdx.x, d = blockIdx.y, n = blockIdx.z;
    const int tid = threadIdx.x;
    __shared__ float ts[32][65];
    for (int ic = 0; ic < 4; ++ic) {
        const int i0 = ic * 32;
#pragma unroll
        for (int r = 0; r < 8; ++r) {
            int e = tid + r * 256;
            int ii = e >> 6, w = e & 63;
            ts[ii][w] = x[((((size_t)n * C_ + i0 + ii) * D_ + d) * H_ + h) * W_ + w];
        }
        __syncthreads();
        int w = tid >> 2, g = tid & 3;
        __half hb[8];
#pragma unroll
        for (int j = 0; j < 8; ++j) hb[j] = __float2half_rn(ts[g * 8 + j][w]);
        __half* dst = g_xT + ((((size_t)n * PD + d + 1) * PH + h + 1) * PW + (w + 1)) * C_ + i0 + g * 8;
        *(uint4*)dst = *(const uint4*)hb;
        __syncthreads();
    }
}

// ---------------------------------------------------------------------------
// Kernel 4: conv as 54 accumulated 128x128x64 fp16 GEMMs on HMMA (wmma).
// CTA = (n, d, h-pair). 8 warps x (64o x 32z), frags persist all stages.
// 3-deep cp.async pipeline, ONE barrier per stage, prefetch 2 stages ahead.
// ---------------------------------------------------------------------------
__global__ __launch_bounds__(256)
void conv_kernel(float* __restrict__ out) {
    const int hb = blockIdx.x, d = blockIdx.y, n = blockIdx.z;
    const int h0 = hb * 2;
    const int tid = threadIdx.x, wid = tid >> 5;

    __shared__ __align__(16) __half XS[3][128 * LDT];   // B: z-rows x i (K-major)
    __shared__ __align__(16) __half WS[3][128 * LDT];   // A: o-rows x i (K-major)

    const int wo = wid >> 2;        // 0..1 -> o block of 64
    const int wz = wid & 3;         // 0..3 -> z block of 32

    wmma::fragment<wmma::accumulator, 16, 16, 16, float> c[4][2];
#pragma unroll
    for (int m = 0; m < 4; ++m)
#pragma unroll
        for (int nn = 0; nn < 2; ++nn) wmma::fill_fragment(c[m][nn], 0.f);

    const __half* xT_n = g_xT + (size_t)n * PD * PH * PW * C_;
    const __half* wm_n = g_wmod + (size_t)n * TAPS * C_ * C_;

    // Per-stage staging: 1024 16B chunks per tile (X and W), 4 per thread each.
    auto prefetch = [&](int s, int buf) {
        const int ic = s >= TAPS;           // 0 or 1
        const int t  = s - ic * TAPS;
        const int kd = t / 9, rr = t - kd * 9;
        const int kh = rr / 3, kw = rr - kh * 3;
        const int i0 = ic * 64;
        const __half* xb = xT_n + (((size_t)(d + kd) * PH + (h0 + kh)) * PW + kw) * C_ + i0;
        const __half* wb = wm_n + (size_t)t * C_ * C_ + i0;
#pragma unroll
        for (int it = 0; it < 4; ++it) {
            int cch = tid + it * 256;
            int row = cch >> 3, q = cch & 7;
            int hh = row >> 6, w = row & 63;
            cp_async16(smem_u32(&XS[buf][row * LDT + q * 8]),
                       xb + ((size_t)(hh * PW + w)) * C_ + q * 8);
            cp_async16(smem_u32(&WS[buf][row * LDT + q * 8]),
                       wb + (size_t)row * C_ + q * 8);
        }
    };

    auto compute = [&](int buf) {
#pragma unroll
        for (int k = 0; k < 4; ++k) {
            wmma::fragment<wmma::matrix_a, 16, 16, 16, __half, wmma::row_major> a[4];
            wmma::fragment<wmma::matrix_b, 16, 16, 16, __half, wmma::col_major> b[2];
#pragma unroll
            for (int nn = 0; nn < 2; ++nn)
                wmma::load_matrix_sync(b[nn], &XS[buf][(wz * 32 + nn * 16) * LDT + k * 16], LDT);
#pragma unroll
            for (int m = 0; m < 4; ++m) {
                wmma::load_matrix_sync(a[m], &WS[buf][(wo * 64 + m * 16) * LDT + k * 16], LDT);
#pragma unroll
                for (int nn = 0; nn < 2; ++nn)
                    wmma::mma_sync(c[m][nn], a[m], b[nn], c[m][nn]);
            }
        }
    };

    // 3-stage pipeline: one barrier per stage.
    prefetch(0, 0); CP_COMMIT();
    prefetch(1, 1); CP_COMMIT();
    int buf = 0;
    for (int s = 0; s < NSTAGE; ++s) {
        if (s < NSTAGE - 2) CP_WAIT(1);   // completes group s (pending: s, s+1)
        else                CP_WAIT(0);   // tail
        __syncthreads();                  // data visible + buf (s-1)%3 free
        if (s + 2 < NSTAGE) {
            int nb = buf + 2; if (nb >= 3) nb -= 3;
            prefetch(s + 2, nb);
            CP_COMMIT();
        }
        compute(buf);
        if (++buf == 3) buf = 0;
    }

    // Epilogue: store 16x16 fragments straight to gmem (z tiles never straddle hh).
#pragma unroll
    for (int m = 0; m < 4; ++m) {
        const int o = wo * 64 + m * 16;
#pragma unroll
        for (int nn = 0; nn < 2; ++nn) {
            const int z = wz * 32 + nn * 16;
            const int hh = z >> 6, w0 = z & 63;
            float* dst = out + (((size_t)n * C_ + o) * D_ + d) * (H_ * W_) + (h0 + hh) * W_ + w0;
            wmma::store_matrix_sync(dst, c[m][nn], D_ * H_ * W_, wmma::mem_row_major);
        }
    }
}

// ---------------------------------------------------------------------------
extern "C" void kernel_launch(void* const* d_in, const int* in_sizes, int n_in,
                              void* d_out, int out_size) {
    const float* x      = (const float*)d_in[0];
    const float* latent = (const float*)d_in[1];
    const float* weight = (const float*)d_in[2];
    const float* fc_w   = (const float*)d_in[3];
    const float* fc_b   = (const float*)d_in[4];
    float* out = (float*)d_out;

    style_kernel<<<dim3(C_ / 4, N_), 128>>>(latent, fc_w, fc_b);
    modw_kernel<<<dim3(C_, N_), C_>>>(weight);
    transpose_kernel<<<dim3(H_, D_, N_), 256>>>(x);
    conv_kernel<<<dim3(H_ / 2, D_, N_), 256>>>(out);
}